// round 12
// baseline (speedup 1.0000x reference)
#include <cuda_runtime.h>
#include <cuda_bf16.h>
#include <math.h>

// ---------------------------------------------------------------------------
// blockLayer: out[b, 3n+k] = x[b,:] . B[n][:,k],  B = M^T M (3x3 symmetric)
// Pure HBM-write-bound (402.6 MB fp32 out). Round 12 = R7 winner with ONE
// change: default-policy stores (plain st.global) instead of __stcs. On a
// write-only stream the L2 (126 MB) can act as a write-combining buffer and
// smooth DRAM write scheduling; .cs (evict-first) bypasses that. Everything
// else identical to the best config: fused make_B from L2-resident w,
// lane-contiguous float4 columns (coalesced STG.128), BT=32 / 3072 blocks
// (multi-wave backfill), unroll 8, __launch_bounds__(256,8) -> 32 regs.
// ---------------------------------------------------------------------------

#define BT 32            // batch rows per block -> 128 tiles -> 3072 blocks
#define TPB 256          // threads per block; each thread owns ONE float4 col

__device__ __forceinline__ float softplus_f(float x) {
    return (x > 20.0f) ? x : log1pf(expf(x));
}

// Compute packed symmetric B = M^T M for weight row wr (6 floats, 8B aligned).
__device__ __forceinline__ void make_B(const float* __restrict__ wr,
                                       float4& lo, float4& hi) {
    float2 p0 = *reinterpret_cast<const float2*>(wr + 0);
    float2 p1 = *reinterpret_cast<const float2*>(wr + 2);
    float2 p2 = *reinterpret_cast<const float2*>(wr + 4);
    float a = softplus_f(p0.x);
    float b = p0.y;
    float c = p1.x;
    float d = softplus_f(p1.y);
    float e = p2.x;
    float f = softplus_f(p2.y);
    lo.x = a * a;                       // B00
    lo.y = a * b;                       // B01
    lo.z = a * c;                       // B02
    lo.w = b * b + d * d;               // B11
    hi.x = b * c + d * e;               // B12
    hi.y = c * c + e * e + f * f;       // B22
    hi.z = 0.0f; hi.w = 0.0f;
}

// Extract column k of symmetric B given packed (lo, hi).
__device__ __forceinline__ void b_col(const float4& lo, const float4& hi, int k,
                                      float& c0, float& c1, float& c2) {
    if (k == 0)      { c0 = lo.x; c1 = lo.y; c2 = lo.z; }
    else if (k == 1) { c0 = lo.y; c1 = lo.w; c2 = hi.x; }
    else             { c0 = lo.z; c1 = hi.x; c2 = hi.y; }
}

__global__ __launch_bounds__(TPB, 8)
void fused_kernel(const float* __restrict__ x, const float* __restrict__ w,
                  float4* __restrict__ out, int batch, int n) {
    __shared__ float sx[BT * 3];

    const int q_row = (3 * n) / 4;           // float4 columns per output row
    const int b0 = blockIdx.y * BT;

    // Stage x tile into smem (BT*3 = 96 floats)
    if (threadIdx.x < BT * 3) {
        int idx = b0 * 3 + threadIdx.x;
        sx[threadIdx.x] = (idx < batch * 3) ? x[idx] : 0.0f;
    }
    __syncthreads();

    // This thread's single float4 output column (lane-contiguous -> coalesced)
    const int q = blockIdx.x * TPB + threadIdx.x;
    if (q >= q_row) return;

    // Derive the (at most) two B matrices this float4 touches, then the
    // batch-invariant coefficients: out4[j] = x0*c0[j] + x1*c1[j] + x2*c2[j]
    float c0[4], c1[4], c2[4];
    {
        int f0 = 4 * q;
        int n0 = f0 / 3;
        int k0 = f0 - 3 * n0;
        int n1 = (n0 + 1 < n) ? (n0 + 1) : (n - 1);
        float4 Alo, Ahi, Clo, Chi;
        make_B(w + (size_t)n0 * 6, Alo, Ahi);
        make_B(w + (size_t)n1 * 6, Clo, Chi);
        #pragma unroll
        for (int j = 0; j < 4; j++) {
            int kk = k0 + j;
            if (kk < 3) b_col(Alo, Ahi, kk,     c0[j], c1[j], c2[j]);
            else        b_col(Clo, Chi, kk - 3, c0[j], c1[j], c2[j]);
        }
    }

    float4* dst = out + (size_t)b0 * q_row + q;
    const size_t stride = q_row;
    const int bmax = (batch - b0 < BT) ? (batch - b0) : BT;

    #pragma unroll 8
    for (int bb = 0; bb < bmax; bb++) {
        float x0 = sx[bb * 3 + 0];
        float x1 = sx[bb * 3 + 1];
        float x2 = sx[bb * 3 + 2];
        float4 v;
        v.x = fmaf(x0, c0[0], fmaf(x1, c1[0], x2 * c2[0]));
        v.y = fmaf(x0, c0[1], fmaf(x1, c1[1], x2 * c2[1]));
        v.z = fmaf(x0, c0[2], fmaf(x1, c1[2], x2 * c2[2]));
        v.w = fmaf(x0, c0[3], fmaf(x1, c1[3], x2 * c2[3]));
        *dst = v;                      // default-policy STG.128 (L2 write-combine)
        dst += stride;
    }
}

extern "C" void kernel_launch(void* const* d_in, const int* in_sizes, int n_in,
                              void* d_out, int out_size) {
    const float* inp = (const float*)d_in[0];   // (batch, 3)
    const float* w   = (const float*)d_in[1];   // (n, 6)
    float4* out = (float4*)d_out;

    int batch = in_sizes[0] / 3;
    int n     = in_sizes[1] / 6;
    int q_row = (3 * n) / 4;

    dim3 grid((q_row + TPB - 1) / TPB, (batch + BT - 1) / BT);
    fused_kernel<<<grid, TPB>>>(inp, w, out, batch, n);
}

// round 13
// speedup vs baseline: 1.0025x; 1.0025x over previous
#include <cuda_runtime.h>
#include <cuda_bf16.h>
#include <math.h>

// ---------------------------------------------------------------------------
// blockLayer: out[b, 3n+k] = x[b,:] . B[n][:,k],  B = M^T M (3x3 symmetric)
// FINAL KERNEL (Round 7 config; best of 12-round search, 61.95-62.5us).
//
// The problem is pure HBM-write-bound: output = 402.6 MB fp32, inputs tiny
// (48 KB + 192 KB), FLOPs negligible. Design:
//  - fused single kernel: B = M^T M derived in-kernel from L2-resident w
//  - lane-contiguous float4 output columns -> perfectly coalesced STG.128
//  - .cs (evict-first) streaming stores (verified better than default, R12)
//  - BT=32 batch tile staged in smem; 3072 blocks = 2.59 waves (multi-wave
//    backfill beats single-wave tail-idle; verified R6 vs R7)
//  - batch loop unrolled x8: 8 independent streaming stores in flight/thread
//  - __launch_bounds__(256,8): 32 regs -> 8 CTAs/SM, ~85% occupancy
//
// Measured at the fp32 streaming-write roofline: DRAM counter 72% (5.7 TB/s),
// wall-clock-implied ~6.7 TB/s (84% of 8 TB/s spec). Seven structural
// variants all pinned at 70-73% DRAM; no remaining lever.
// ---------------------------------------------------------------------------

#define BT 32            // batch rows per block -> 128 tiles -> 3072 blocks
#define TPB 256          // threads per block; each thread owns ONE float4 col

__device__ __forceinline__ float softplus_f(float x) {
    return (x > 20.0f) ? x : log1pf(expf(x));
}

// Compute packed symmetric B = M^T M for weight row wr (6 floats, 8B aligned).
__device__ __forceinline__ void make_B(const float* __restrict__ wr,
                                       float4& lo, float4& hi) {
    float2 p0 = *reinterpret_cast<const float2*>(wr + 0);
    float2 p1 = *reinterpret_cast<const float2*>(wr + 2);
    float2 p2 = *reinterpret_cast<const float2*>(wr + 4);
    float a = softplus_f(p0.x);
    float b = p0.y;
    float c = p1.x;
    float d = softplus_f(p1.y);
    float e = p2.x;
    float f = softplus_f(p2.y);
    lo.x = a * a;                       // B00
    lo.y = a * b;                       // B01
    lo.z = a * c;                       // B02
    lo.w = b * b + d * d;               // B11
    hi.x = b * c + d * e;               // B12
    hi.y = c * c + e * e + f * f;       // B22
    hi.z = 0.0f; hi.w = 0.0f;
}

// Extract column k of symmetric B given packed (lo, hi).
__device__ __forceinline__ void b_col(const float4& lo, const float4& hi, int k,
                                      float& c0, float& c1, float& c2) {
    if (k == 0)      { c0 = lo.x; c1 = lo.y; c2 = lo.z; }
    else if (k == 1) { c0 = lo.y; c1 = lo.w; c2 = hi.x; }
    else             { c0 = lo.z; c1 = hi.x; c2 = hi.y; }
}

__global__ __launch_bounds__(TPB, 8)
void fused_kernel(const float* __restrict__ x, const float* __restrict__ w,
                  float4* __restrict__ out, int batch, int n) {
    __shared__ float sx[BT * 3];

    const int q_row = (3 * n) / 4;           // float4 columns per output row
    const int b0 = blockIdx.y * BT;

    // Stage x tile into smem (BT*3 = 96 floats)
    if (threadIdx.x < BT * 3) {
        int idx = b0 * 3 + threadIdx.x;
        sx[threadIdx.x] = (idx < batch * 3) ? x[idx] : 0.0f;
    }
    __syncthreads();

    // This thread's single float4 output column (lane-contiguous -> coalesced)
    const int q = blockIdx.x * TPB + threadIdx.x;
    if (q >= q_row) return;

    // Derive the (at most) two B matrices this float4 touches, then the
    // batch-invariant coefficients: out4[j] = x0*c0[j] + x1*c1[j] + x2*c2[j]
    float c0[4], c1[4], c2[4];
    {
        int f0 = 4 * q;
        int n0 = f0 / 3;
        int k0 = f0 - 3 * n0;
        int n1 = (n0 + 1 < n) ? (n0 + 1) : (n - 1);
        float4 Alo, Ahi, Clo, Chi;
        make_B(w + (size_t)n0 * 6, Alo, Ahi);
        make_B(w + (size_t)n1 * 6, Clo, Chi);
        #pragma unroll
        for (int j = 0; j < 4; j++) {
            int kk = k0 + j;
            if (kk < 3) b_col(Alo, Ahi, kk,     c0[j], c1[j], c2[j]);
            else        b_col(Clo, Chi, kk - 3, c0[j], c1[j], c2[j]);
        }
    }

    float4* dst = out + (size_t)b0 * q_row + q;
    const size_t stride = q_row;
    const int bmax = (batch - b0 < BT) ? (batch - b0) : BT;

    #pragma unroll 8
    for (int bb = 0; bb < bmax; bb++) {
        float x0 = sx[bb * 3 + 0];
        float x1 = sx[bb * 3 + 1];
        float x2 = sx[bb * 3 + 2];
        float4 v;
        v.x = fmaf(x0, c0[0], fmaf(x1, c1[0], x2 * c2[0]));
        v.y = fmaf(x0, c0[1], fmaf(x1, c1[1], x2 * c2[1]));
        v.z = fmaf(x0, c0[2], fmaf(x1, c1[2], x2 * c2[2]));
        v.w = fmaf(x0, c0[3], fmaf(x1, c1[3], x2 * c2[3]));
        __stcs(dst, v);
        dst += stride;
    }
}

extern "C" void kernel_launch(void* const* d_in, const int* in_sizes, int n_in,
                              void* d_out, int out_size) {
    const float* inp = (const float*)d_in[0];   // (batch, 3)
    const float* w   = (const float*)d_in[1];   // (n, 6)
    float4* out = (float4*)d_out;

    int batch = in_sizes[0] / 3;
    int n     = in_sizes[1] / 6;
    int q_row = (3 * n) / 4;

    dim3 grid((q_row + TPB - 1) / TPB, (batch + BT - 1) / BT);
    fused_kernel<<<grid, TPB>>>(inp, w, out, batch, n);
}

// round 14
// speedup vs baseline: 1.0253x; 1.0227x over previous
#include <cuda_runtime.h>
#include <cuda_bf16.h>
#include <math.h>

// ---------------------------------------------------------------------------
// blockLayer: out[b, 3n+k] = x[b,:] . B[n][:,k],  B = M^T M (3x3 symmetric)
// FINAL KERNEL (Round 7 config; best of 13-round search; kernel ~60us stable,
// total 62.0-63.4us run-to-run noise).
//
// The problem is pure HBM-write-bound: output = 402.6 MB fp32, inputs tiny
// (48 KB + 192 KB), FLOPs negligible. Design:
//  - fused single kernel: B = M^T M derived in-kernel from L2-resident w
//  - lane-contiguous float4 output columns -> perfectly coalesced STG.128
//    (the only fully-dense store mapping; wider per-thread spans tested and
//    regressed via half-dense L1 wavefronts)
//  - .cs (evict-first) streaming stores (verified better than default, R12)
//  - BT=32 batch tile staged in smem; 3072 blocks = 2.59 waves (multi-wave
//    backfill beats single-wave tail-idle; verified R6 vs R7)
//  - batch loop unrolled x8: 8 independent streaming stores in flight/thread
//  - __launch_bounds__(256,8): 32 regs -> 8 CTAs/SM, ~85% occupancy
//
// At the fp32 streaming-write roofline: DRAM counter 72% (5.7 TB/s),
// wall-clock-implied ~6.7 TB/s (84% of 8 TB/s spec). Seven structural
// variants all pinned at 70-73% DRAM; no remaining lever above noise.
// ---------------------------------------------------------------------------

#define BT 32            // batch rows per block -> 128 tiles -> 3072 blocks
#define TPB 256          // threads per block; each thread owns ONE float4 col

__device__ __forceinline__ float softplus_f(float x) {
    return (x > 20.0f) ? x : log1pf(expf(x));
}

// Compute packed symmetric B = M^T M for weight row wr (6 floats, 8B aligned).
__device__ __forceinline__ void make_B(const float* __restrict__ wr,
                                       float4& lo, float4& hi) {
    float2 p0 = *reinterpret_cast<const float2*>(wr + 0);
    float2 p1 = *reinterpret_cast<const float2*>(wr + 2);
    float2 p2 = *reinterpret_cast<const float2*>(wr + 4);
    float a = softplus_f(p0.x);
    float b = p0.y;
    float c = p1.x;
    float d = softplus_f(p1.y);
    float e = p2.x;
    float f = softplus_f(p2.y);
    lo.x = a * a;                       // B00
    lo.y = a * b;                       // B01
    lo.z = a * c;                       // B02
    lo.w = b * b + d * d;               // B11
    hi.x = b * c + d * e;               // B12
    hi.y = c * c + e * e + f * f;       // B22
    hi.z = 0.0f; hi.w = 0.0f;
}

// Extract column k of symmetric B given packed (lo, hi).
__device__ __forceinline__ void b_col(const float4& lo, const float4& hi, int k,
                                      float& c0, float& c1, float& c2) {
    if (k == 0)      { c0 = lo.x; c1 = lo.y; c2 = lo.z; }
    else if (k == 1) { c0 = lo.y; c1 = lo.w; c2 = hi.x; }
    else             { c0 = lo.z; c1 = hi.x; c2 = hi.y; }
}

__global__ __launch_bounds__(TPB, 8)
void fused_kernel(const float* __restrict__ x, const float* __restrict__ w,
                  float4* __restrict__ out, int batch, int n) {
    __shared__ float sx[BT * 3];

    const int q_row = (3 * n) / 4;           // float4 columns per output row
    const int b0 = blockIdx.y * BT;

    // Stage x tile into smem (BT*3 = 96 floats)
    if (threadIdx.x < BT * 3) {
        int idx = b0 * 3 + threadIdx.x;
        sx[threadIdx.x] = (idx < batch * 3) ? x[idx] : 0.0f;
    }
    __syncthreads();

    // This thread's single float4 output column (lane-contiguous -> coalesced)
    const int q = blockIdx.x * TPB + threadIdx.x;
    if (q >= q_row) return;

    // Derive the (at most) two B matrices this float4 touches, then the
    // batch-invariant coefficients: out4[j] = x0*c0[j] + x1*c1[j] + x2*c2[j]
    float c0[4], c1[4], c2[4];
    {
        int f0 = 4 * q;
        int n0 = f0 / 3;
        int k0 = f0 - 3 * n0;
        int n1 = (n0 + 1 < n) ? (n0 + 1) : (n - 1);
        float4 Alo, Ahi, Clo, Chi;
        make_B(w + (size_t)n0 * 6, Alo, Ahi);
        make_B(w + (size_t)n1 * 6, Clo, Chi);
        #pragma unroll
        for (int j = 0; j < 4; j++) {
            int kk = k0 + j;
            if (kk < 3) b_col(Alo, Ahi, kk,     c0[j], c1[j], c2[j]);
            else        b_col(Clo, Chi, kk - 3, c0[j], c1[j], c2[j]);
        }
    }

    float4* dst = out + (size_t)b0 * q_row + q;
    const size_t stride = q_row;
    const int bmax = (batch - b0 < BT) ? (batch - b0) : BT;

    #pragma unroll 8
    for (int bb = 0; bb < bmax; bb++) {
        float x0 = sx[bb * 3 + 0];
        float x1 = sx[bb * 3 + 1];
        float x2 = sx[bb * 3 + 2];
        float4 v;
        v.x = fmaf(x0, c0[0], fmaf(x1, c1[0], x2 * c2[0]));
        v.y = fmaf(x0, c0[1], fmaf(x1, c1[1], x2 * c2[1]));
        v.z = fmaf(x0, c0[2], fmaf(x1, c1[2], x2 * c2[2]));
        v.w = fmaf(x0, c0[3], fmaf(x1, c1[3], x2 * c2[3]));
        __stcs(dst, v);
        dst += stride;
    }
}

extern "C" void kernel_launch(void* const* d_in, const int* in_sizes, int n_in,
                              void* d_out, int out_size) {
    const float* inp = (const float*)d_in[0];   // (batch, 3)
    const float* w   = (const float*)d_in[1];   // (n, 6)
    float4* out = (float4*)d_out;

    int batch = in_sizes[0] / 3;
    int n     = in_sizes[1] / 6;
    int q_row = (3 * n) / 4;

    dim3 grid((q_row + TPB - 1) / TPB, (batch + BT - 1) / BT);
    fused_kernel<<<grid, TPB>>>(inp, w, out, batch, n);
}

// round 15
// speedup vs baseline: 1.0258x; 1.0005x over previous
#include <cuda_runtime.h>
#include <cuda_bf16.h>
#include <math.h>

// ---------------------------------------------------------------------------
// blockLayer: out[b, 3n+k] = x[b,:] . B[n][:,k],  B = M^T M (3x3 symmetric)
// FINAL KERNEL — converged winner (4 runs: 61.95/62.53/63.36/61.95us total;
// kernel 59.7-60.2us stable).
//
// The problem is pure HBM-write-bound: output = 402.6 MB fp32, inputs tiny
// (48 KB + 192 KB), FLOPs negligible. Design:
//  - fused single kernel: B = M^T M derived in-kernel from L2-resident w
//  - lane-contiguous float4 output columns -> perfectly coalesced STG.128
//  - .cs (evict-first) streaming stores (verified better than default)
//  - BT=32 batch tile staged in smem; 3072 blocks = 2.59 waves (multi-wave
//    backfill beats single-wave tail-idle on this chip)
//  - batch loop unrolled x8: 8 independent streaming stores in flight/thread
//  - __launch_bounds__(256,8): 32 regs -> 8 CTAs/SM, ~85% occupancy
//
// At the fp32 streaming-write roofline: DRAM counter 72% (5.75 TB/s),
// wall-clock-implied ~6.7 TB/s (84% of 8 TB/s spec). Seven structural
// variants all pinned at 70-73% DRAM; no remaining lever above noise.
// ---------------------------------------------------------------------------

#define BT 32            // batch rows per block -> 128 tiles -> 3072 blocks
#define TPB 256          // threads per block; each thread owns ONE float4 col

__device__ __forceinline__ float softplus_f(float x) {
    return (x > 20.0f) ? x : log1pf(expf(x));
}

// Compute packed symmetric B = M^T M for weight row wr (6 floats, 8B aligned).
__device__ __forceinline__ void make_B(const float* __restrict__ wr,
                                       float4& lo, float4& hi) {
    float2 p0 = *reinterpret_cast<const float2*>(wr + 0);
    float2 p1 = *reinterpret_cast<const float2*>(wr + 2);
    float2 p2 = *reinterpret_cast<const float2*>(wr + 4);
    float a = softplus_f(p0.x);
    float b = p0.y;
    float c = p1.x;
    float d = softplus_f(p1.y);
    float e = p2.x;
    float f = softplus_f(p2.y);
    lo.x = a * a;                       // B00
    lo.y = a * b;                       // B01
    lo.z = a * c;                       // B02
    lo.w = b * b + d * d;               // B11
    hi.x = b * c + d * e;               // B12
    hi.y = c * c + e * e + f * f;       // B22
    hi.z = 0.0f; hi.w = 0.0f;
}

// Extract column k of symmetric B given packed (lo, hi).
__device__ __forceinline__ void b_col(const float4& lo, const float4& hi, int k,
                                      float& c0, float& c1, float& c2) {
    if (k == 0)      { c0 = lo.x; c1 = lo.y; c2 = lo.z; }
    else if (k == 1) { c0 = lo.y; c1 = lo.w; c2 = hi.x; }
    else             { c0 = lo.z; c1 = hi.x; c2 = hi.y; }
}

__global__ __launch_bounds__(TPB, 8)
void fused_kernel(const float* __restrict__ x, const float* __restrict__ w,
                  float4* __restrict__ out, int batch, int n) {
    __shared__ float sx[BT * 3];

    const int q_row = (3 * n) / 4;           // float4 columns per output row
    const int b0 = blockIdx.y * BT;

    // Stage x tile into smem (BT*3 = 96 floats)
    if (threadIdx.x < BT * 3) {
        int idx = b0 * 3 + threadIdx.x;
        sx[threadIdx.x] = (idx < batch * 3) ? x[idx] : 0.0f;
    }
    __syncthreads();

    // This thread's single float4 output column (lane-contiguous -> coalesced)
    const int q = blockIdx.x * TPB + threadIdx.x;
    if (q >= q_row) return;

    // Derive the (at most) two B matrices this float4 touches, then the
    // batch-invariant coefficients: out4[j] = x0*c0[j] + x1*c1[j] + x2*c2[j]
    float c0[4], c1[4], c2[4];
    {
        int f0 = 4 * q;
        int n0 = f0 / 3;
        int k0 = f0 - 3 * n0;
        int n1 = (n0 + 1 < n) ? (n0 + 1) : (n - 1);
        float4 Alo, Ahi, Clo, Chi;
        make_B(w + (size_t)n0 * 6, Alo, Ahi);
        make_B(w + (size_t)n1 * 6, Clo, Chi);
        #pragma unroll
        for (int j = 0; j < 4; j++) {
            int kk = k0 + j;
            if (kk < 3) b_col(Alo, Ahi, kk,     c0[j], c1[j], c2[j]);
            else        b_col(Clo, Chi, kk - 3, c0[j], c1[j], c2[j]);
        }
    }

    float4* dst = out + (size_t)b0 * q_row + q;
    const size_t stride = q_row;
    const int bmax = (batch - b0 < BT) ? (batch - b0) : BT;

    #pragma unroll 8
    for (int bb = 0; bb < bmax; bb++) {
        float x0 = sx[bb * 3 + 0];
        float x1 = sx[bb * 3 + 1];
        float x2 = sx[bb * 3 + 2];
        float4 v;
        v.x = fmaf(x0, c0[0], fmaf(x1, c1[0], x2 * c2[0]));
        v.y = fmaf(x0, c0[1], fmaf(x1, c1[1], x2 * c2[1]));
        v.z = fmaf(x0, c0[2], fmaf(x1, c1[2], x2 * c2[2]));
        v.w = fmaf(x0, c0[3], fmaf(x1, c1[3], x2 * c2[3]));
        __stcs(dst, v);
        dst += stride;
    }
}

extern "C" void kernel_launch(void* const* d_in, const int* in_sizes, int n_in,
                              void* d_out, int out_size) {
    const float* inp = (const float*)d_in[0];   // (batch, 3)
    const float* w   = (const float*)d_in[1];   // (n, 6)
    float4* out = (float4*)d_out;

    int batch = in_sizes[0] / 3;
    int n     = in_sizes[1] / 6;
    int q_row = (3 * n) / 4;

    dim3 grid((q_row + TPB - 1) / TPB, (batch + BT - 1) / BT);
    fused_kernel<<<grid, TPB>>>(inp, w, out, batch, n);
}